// round 9
// baseline (speedup 1.0000x reference)
#include <cuda_runtime.h>
#include <cuda_bf16.h>

#define NN 100000
#define EE 1600000
#define EPS 1e-5f
#define NB1 196        // ceil(NN/512)

typedef unsigned long long ull;

// ---------------- scratch ---------------------------------------------------
__device__ float g_bufA[NN * 256];     // MLP hidden raw (track A only)
__device__ float g_A1[NN * 256];       // [agg_r0|agg_r1|agg_r2|h_in] (track B)
__device__ float g_zmlp[NN * 128];     // raw mlp2 output (BN fused into k_final)
__device__ float g_t2[(long)NN * 512]; // t = BN(z1) @ [Wr0|Wr1|Wr2|Wroot]
__device__ float g_agg1[NN * 128];     // raw rgcn1 output z1
__device__ float g_agg2[NN * 128];     // raw z2 (BN fused into k_final)
__device__ float g_wcat[256 * 128 + 128 * 512];
__device__ float g_bias2[512];
__device__ float g_sum[4 * 256];
__device__ float g_sq[4 * 256];
__device__ int   g_hist[NN];
__device__ int   g_row[NN];
__device__ int   g_cur[NN];
__device__ int   g_incl[NN];
__device__ int   g_bsum[256];
__device__ int   g_packed[EE];         // src | (rel<<20)

// ---------------- mma / ldmatrix helpers -------------------------------------
__device__ __forceinline__ void mma_bf16(float* d, const unsigned* a, unsigned b0, unsigned b1) {
    asm volatile(
        "mma.sync.aligned.m16n8k16.row.col.f32.bf16.bf16.f32 "
        "{%0,%1,%2,%3}, {%4,%5,%6,%7}, {%8,%9}, {%0,%1,%2,%3};"
        : "+f"(d[0]), "+f"(d[1]), "+f"(d[2]), "+f"(d[3])
        : "r"(a[0]), "r"(a[1]), "r"(a[2]), "r"(a[3]), "r"(b0), "r"(b1));
}
__device__ __forceinline__ void ldsm_x4(unsigned* r, unsigned a) {
    asm volatile("ldmatrix.sync.aligned.m8n8.x4.shared.b16 {%0,%1,%2,%3}, [%4];"
                 : "=r"(r[0]), "=r"(r[1]), "=r"(r[2]), "=r"(r[3]) : "r"(a));
}
__device__ __forceinline__ void ldsm_x4_t(unsigned* r, unsigned a) {
    asm volatile("ldmatrix.sync.aligned.m8n8.x4.trans.shared.b16 {%0,%1,%2,%3}, [%4];"
                 : "=r"(r[0]), "=r"(r[1]), "=r"(r[2]), "=r"(r[3]) : "r"(a));
}
__device__ __forceinline__ unsigned short bfh(float x) {
    return __bfloat16_as_ushort(__float2bfloat16_rn(x));
}
__device__ __forceinline__ float bff(unsigned short u) {
    return __bfloat162float(__ushort_as_bfloat16(u));
}
// split float4 into hi ull (4 bf16) and lo ull (4 bf16)
__device__ __forceinline__ void split4(float4 v, ull& hu, ull& lu) {
    unsigned short h0 = bfh(v.x), h1 = bfh(v.y), h2 = bfh(v.z), h3 = bfh(v.w);
    unsigned short l0 = bfh(v.x - bff(h0));
    unsigned short l1 = bfh(v.y - bff(h1));
    unsigned short l2 = bfh(v.z - bff(h2));
    unsigned short l3 = bfh(v.w - bff(h3));
    hu = (ull)h0 | ((ull)h1 << 16) | ((ull)h2 << 32) | ((ull)h3 << 48);
    lu = (ull)l0 | ((ull)l1 << 16) | ((ull)l2 << 32) | ((ull)l3 << 48);
}

// ---------------- utility ---------------------------------------------------
__global__ void k_zero_i(int* p, int n) {
    int i = blockIdx.x * blockDim.x + threadIdx.x;
    if (i < n) p[i] = 0;
}
__global__ void k_zero_f2(float* p, float* q, int n) {
    int i = blockIdx.x * blockDim.x + threadIdx.x;
    if (i < n) { p[i] = 0.0f; q[i] = 0.0f; }
}
__global__ void k_prep_w(const float* __restrict__ r1rel, const float* __restrict__ r1root,
                         const float* __restrict__ r2rel, const float* __restrict__ r2root,
                         const float* __restrict__ rg2b) {
    int i = blockIdx.x * blockDim.x + threadIdx.x;
    if (i < 3 * 64 * 128) g_wcat[i] = r1rel[i];
    else if (i < 4 * 64 * 128) g_wcat[i] = r1root[i - 3 * 64 * 128];
    if (i < 3 * 128 * 128) {
        int r = i >> 14;
        int rem = i & 16383;
        int k = rem >> 7, j = rem & 127;
        g_wcat[256 * 128 + k * 512 + r * 128 + j] = r2rel[i];
    }
    if (i < 128 * 128) {
        int k = i >> 7, j = i & 127;
        g_wcat[256 * 128 + k * 512 + 384 + j] = r2root[i];
    }
    if (i < 512) g_bias2[i] = (i >= 384) ? rg2b[i - 384] : 0.0f;
}

// ---------------- CSR build --------------------------------------------------
__global__ void k_hist(const int* __restrict__ dst) {
    int i = blockIdx.x * blockDim.x + threadIdx.x;
    if (i < EE) atomicAdd(&g_hist[dst[i]], 1);
}
__global__ void k_scan1() {
    __shared__ int sm[512];
    int i = blockIdx.x * 512 + threadIdx.x;
    int v = (i < NN) ? g_hist[i] : 0;
    sm[threadIdx.x] = v;
    __syncthreads();
    for (int off = 1; off < 512; off <<= 1) {
        int t = (threadIdx.x >= off) ? sm[threadIdx.x - off] : 0;
        __syncthreads();
        sm[threadIdx.x] += t;
        __syncthreads();
    }
    if (i < NN) g_incl[i] = sm[threadIdx.x];
    if (threadIdx.x == 511) g_bsum[blockIdx.x] = sm[511];
}
__global__ void k_scan2() {
    __shared__ int sm[256];
    int t = threadIdx.x;
    int v = (t < NB1) ? g_bsum[t] : 0;
    sm[t] = v;
    __syncthreads();
    for (int off = 1; off < 256; off <<= 1) {
        int u = (t >= off) ? sm[t - off] : 0;
        __syncthreads();
        sm[t] += u;
        __syncthreads();
    }
    if (t < NB1) g_bsum[t] = sm[t] - v;  // exclusive
}
__global__ void k_scan3() {
    int i = blockIdx.x * 512 + threadIdx.x;
    if (i >= NN) return;
    int r = g_incl[i] - g_hist[i] + g_bsum[blockIdx.x];
    g_row[i] = r;
    g_cur[i] = r;
}
__global__ void k_place(const int* __restrict__ src, const int* __restrict__ dst,
                        const int* __restrict__ et) {
    int i = blockIdx.x * blockDim.x + threadIdx.x;
    if (i >= EE) return;
    int pos = atomicAdd(&g_cur[dst[i]], 1);
    g_packed[pos] = src[i] | (et[i] << 20);
}

// ------- GEMM: bf16 3-term split mma.sync, fused stats + A-side BN ----------
// Tile 128x128, BK=32, 256 threads (8 warps, 2x4), warp tile 64x32.
// smem per buffer: Ah[128][40]bf16(10240) Al(10240) Bh[32][136]bf16(8704) Bl(8704) = 37888
#define SM_BUF 37888
#define SM_TOTAL (2 * SM_BUF)

__global__ __launch_bounds__(256)
void sgemm_bias(const float* __restrict__ A, const float* __restrict__ B,
                const float* __restrict__ bias, float* __restrict__ C,
                int M, int K, int Nc, int lda,
                float* sumP, float* sqP,
                const float* __restrict__ aSc, const float* __restrict__ aSh) {
    extern __shared__ char smem[];
    __shared__ float csum[128];
    __shared__ float csq[128];
    unsigned sbase = (unsigned)__cvta_generic_to_shared(smem);

    const int tid = threadIdx.x;
    const int lane = tid & 31, wid = tid >> 5;
    const int rowBase = blockIdx.y * 128;
    const int colBase = blockIdx.x * 128;

    if (sumP && tid < 128) { csum[tid] = 0.0f; csq[tid] = 0.0f; }

    // loader mapping
    const int aM = tid & 127;
    const int aH = (tid >> 7) * 16;     // k-half base (0 or 16)
    const int bK = tid & 31;
    const int bN = (tid >> 5) * 16;
    const int growA = rowBase + aM;

    float4 rA[4], rB[4];

    auto loadG = [&](int k0) {
#pragma unroll
        for (int i = 0; i < 4; i++) {
            int kk = k0 + aH + i * 4;
            float4 v = make_float4(0.f, 0.f, 0.f, 0.f);
            if (growA < M) {
                v = *(const float4*)&A[(long)growA * lda + kk];
                if (aSc) {
                    v.x = fmaxf(fmaf(v.x, aSc[kk + 0], aSh[kk + 0]), 0.0f);
                    v.y = fmaxf(fmaf(v.y, aSc[kk + 1], aSh[kk + 1]), 0.0f);
                    v.z = fmaxf(fmaf(v.z, aSc[kk + 2], aSh[kk + 2]), 0.0f);
                    v.w = fmaxf(fmaf(v.w, aSc[kk + 3], aSh[kk + 3]), 0.0f);
                }
            }
            rA[i] = v;
            rB[i] = *(const float4*)&B[(long)(k0 + bK) * Nc + colBase + bN + i * 4];
        }
    };
    auto storeS = [&](int buf) {
        char* base = smem + buf * SM_BUF;
#pragma unroll
        for (int i = 0; i < 4; i++) {
            ull hu, lu;
            split4(rA[i], hu, lu);
            int offA = (aM * 40 + aH + i * 4) * 2;
            *(ull*)(base + offA) = hu;
            *(ull*)(base + 10240 + offA) = lu;
            split4(rB[i], hu, lu);
            int offB = (bK * 136 + bN + i * 4) * 2;
            *(ull*)(base + 20480 + offB) = hu;
            *(ull*)(base + 29184 + offB) = lu;
        }
    };

    float acc[4][4][4];
#pragma unroll
    for (int a = 0; a < 4; a++)
#pragma unroll
        for (int b = 0; b < 4; b++)
#pragma unroll
            for (int c = 0; c < 4; c++) acc[a][b][c] = 0.0f;

    const int m0w = (wid & 1) * 64;
    const int n0w = (wid >> 1) * 32;
    const int lr = lane & 15;
    const int lk = (lane >> 4) * 8;

    loadG(0);
    storeS(0);
    __syncthreads();

    int S = K / 32;
    for (int s = 0; s < S; s++) {
        int cur = s & 1;
        if (s + 1 < S) loadG((s + 1) * 32);
        unsigned bb = sbase + cur * SM_BUF;
#pragma unroll
        for (int ks = 0; ks < 32; ks += 16) {
            unsigned Bh[2][4], Bl[2][4];
#pragma unroll
            for (int np = 0; np < 2; np++) {
                unsigned bo = bb + 20480 + ((ks + lr) * 136 + n0w + np * 16 + lk) * 2;
                ldsm_x4_t(Bh[np], bo);
                ldsm_x4_t(Bl[np], bo + 8704);
            }
#pragma unroll
            for (int mf = 0; mf < 4; mf++) {
                unsigned Ah[4], Al[4];
                unsigned ao = bb + ((m0w + mf * 16 + lr) * 40 + ks + lk) * 2;
                ldsm_x4(Ah, ao);
                ldsm_x4(Al, ao + 10240);
#pragma unroll
                for (int nf = 0; nf < 4; nf++) {
                    int np = nf >> 1, h = (nf & 1) * 2;
                    mma_bf16(acc[mf][nf], Ah, Bh[np][h], Bh[np][h + 1]);
                    mma_bf16(acc[mf][nf], Ah, Bl[np][h], Bl[np][h + 1]);
                    mma_bf16(acc[mf][nf], Al, Bh[np][h], Bh[np][h + 1]);
                }
            }
        }
        if (s + 1 < S) storeS((s + 1) & 1);
        __syncthreads();
    }

    // epilogue
    const int g = lane >> 2;
    const int c2 = (lane & 3) * 2;
#pragma unroll
    for (int nf = 0; nf < 4; nf++) {
        int col = colBase + n0w + nf * 8 + c2;
        float bv0 = bias[col], bv1 = bias[col + 1];
        float s0 = 0.f, q0 = 0.f, s1 = 0.f, q1 = 0.f;
#pragma unroll
        for (int mf = 0; mf < 4; mf++)
#pragma unroll
            for (int half = 0; half < 2; half++) {
                int row = rowBase + m0w + mf * 16 + g + half * 8;
                if (row < M) {
                    float v0 = acc[mf][nf][half * 2 + 0] + bv0;
                    float v1 = acc[mf][nf][half * 2 + 1] + bv1;
                    *(float2*)&C[(long)row * Nc + col] = make_float2(v0, v1);
                    s0 += v0; q0 += v0 * v0;
                    s1 += v1; q1 += v1 * v1;
                }
            }
        if (sumP) {
            int lc = n0w + nf * 8 + c2;
            atomicAdd(&csum[lc], s0);
            atomicAdd(&csq[lc], q0);
            atomicAdd(&csum[lc + 1], s1);
            atomicAdd(&csq[lc + 1], q1);
        }
    }
    if (sumP) {
        __syncthreads();
        if (tid < 128) {
            atomicAdd(&sumP[colBase + tid], csum[tid]);
            atomicAdd(&sqP[colBase + tid], csq[tid]);
        }
    }
}

// ---------------- BN prep ----------------------------------------------------
__global__ void k_bnprep(float* sum, float* sq, const float* __restrict__ g,
                         const float* __restrict__ b, int C) {
    int c = threadIdx.x;
    if (c >= C) return;
    const float invN = 1.0f / (float)NN;
    float m = sum[c] * invN;
    float var = sq[c] * invN - m * m;
    float sc = g[c] * rsqrtf(var + EPS);
    float sh = b[c] - m * sc;
    sum[c] = sc;
    sq[c] = sh;
}

// ---------------- ASDA (CSR, warp per node) ---------------------------------
__global__ __launch_bounds__(256)
void k_asda(const float* __restrict__ x, const float* __restrict__ hsd) {
    int node = (blockIdx.x * blockDim.x + threadIdx.x) >> 5;
    int lane = threadIdx.x & 31;
    if (node >= NN) return;
    int start = g_row[node];
    int end = start + g_hist[node];
    float hd = hsd[node];

    float den = 0.f;
    for (int base = start; base < end; base += 32) {
        int idx = base + lane;
        float e = 0.f;
        if (idx < end) {
            int s = g_packed[idx] & 0xFFFFF;
            e = __expf((hsd[s] - hd) * 10.0f);
        }
        den += e;
    }
#pragma unroll
    for (int o = 16; o > 0; o >>= 1) den += __shfl_xor_sync(0xffffffffu, den, o);
    float inv = 1.0f / fmaxf(den, 1e-9f);

    float a0 = x[(long)node * 64 + lane];
    float a1 = x[(long)node * 64 + 32 + lane];
    for (int base = start; base < end; base += 32) {
        int idx = base + lane;
        int v = 0;
        float al = 0.f;
        if (idx < end) {
            v = g_packed[idx];
            int s = v & 0xFFFFF;
            al = __expf((hsd[s] - hd) * 10.0f) * inv;
        }
        int m = min(32, end - base);
        for (int j = 0; j < m; j++) {
            int vv = __shfl_sync(0xffffffffu, v, j);
            float aa = __shfl_sync(0xffffffffu, al, j);
            int s = vv & 0xFFFFF;
            a0 = fmaf(aa, x[(long)s * 64 + lane], a0);
            a1 = fmaf(aa, x[(long)s * 64 + 32 + lane], a1);
        }
    }
    g_A1[(long)node * 256 + 192 + lane] = a0;
    g_A1[(long)node * 256 + 224 + lane] = a1;
}

// ---------------- RGCN layer-1 input aggregation (dim 64) --------------------
__global__ __launch_bounds__(256)
void k_agg1() {
    int node = (blockIdx.x * blockDim.x + threadIdx.x) >> 5;
    int lane = threadIdx.x & 31;
    if (node >= NN) return;
    int start = g_row[node];
    int end = start + g_hist[node];

    float a00 = 0, a01 = 0, a10 = 0, a11 = 0, a20 = 0, a21 = 0;
    int c0 = 0, c1 = 0, c2 = 0;
    for (int base = start; base < end; base += 32) {
        int idx = base + lane;
        int v = (idx < end) ? g_packed[idx] : 0;
        int m = min(32, end - base);
        for (int j = 0; j < m; j++) {
            int vv = __shfl_sync(0xffffffffu, v, j);
            int s = vv & 0xFFFFF;
            int r = vv >> 20;
            float f0 = g_A1[(long)s * 256 + 192 + lane];
            float f1 = g_A1[(long)s * 256 + 224 + lane];
            if (r == 0)      { a00 += f0; a01 += f1; c0++; }
            else if (r == 1) { a10 += f0; a11 += f1; c1++; }
            else             { a20 += f0; a21 += f1; c2++; }
        }
    }
    float w0 = 1.0f / (float)max(c0, 1);
    float w1 = 1.0f / (float)max(c1, 1);
    float w2 = 1.0f / (float)max(c2, 1);
    long b = (long)node * 256;
    g_A1[b + 0 + lane] = a00 * w0;  g_A1[b + 32 + lane] = a01 * w0;
    g_A1[b + 64 + lane] = a10 * w1; g_A1[b + 96 + lane] = a11 * w1;
    g_A1[b + 128 + lane] = a20 * w2; g_A1[b + 160 + lane] = a21 * w2;
}

// ------- layer-2: single-pass gather of t, assemble z2, fused BN2 stats ------
__global__ __launch_bounds__(256)
void k_gather2(const float* __restrict__ t, float* __restrict__ z2,
               float* sumP, float* sqP) {
    __shared__ float ss[128];
    __shared__ float sqs[128];
    int tid = threadIdx.x;
    if (tid < 128) { ss[tid] = 0.0f; sqs[tid] = 0.0f; }
    __syncthreads();

    int node = (blockIdx.x * blockDim.x + tid) >> 5;   // grid exact
    int lane = tid & 31;
    int start = g_row[node];
    int end = start + g_hist[node];

    float acc[3][4] = {};
    int cnt[3] = {0, 0, 0};
    for (int base = start; base < end; base += 32) {
        int idx = base + lane;
        int v = (idx < end) ? g_packed[idx] : 0;
        int m = min(32, end - base);
        for (int j = 0; j < m; j++) {
            int vv = __shfl_sync(0xffffffffu, v, j);
            int s = vv & 0xFFFFF;
            int r = vv >> 20;
            const float* tp = t + (long)s * 512 + r * 128;
            float f0 = tp[lane], f1 = tp[32 + lane], f2 = tp[64 + lane], f3 = tp[96 + lane];
            if (r == 0)      { acc[0][0] += f0; acc[0][1] += f1; acc[0][2] += f2; acc[0][3] += f3; cnt[0]++; }
            else if (r == 1) { acc[1][0] += f0; acc[1][1] += f1; acc[1][2] += f2; acc[1][3] += f3; cnt[1]++; }
            else             { acc[2][0] += f0; acc[2][1] += f1; acc[2][2] += f2; acc[2][3] += f3; cnt[2]++; }
        }
    }
    float w0 = 1.0f / (float)max(cnt[0], 1);
    float w1 = 1.0f / (float)max(cnt[1], 1);
    float w2 = 1.0f / (float)max(cnt[2], 1);
    const float* tr = t + (long)node * 512 + 384;
    float o0 = acc[0][0] * w0 + acc[1][0] * w1 + acc[2][0] * w2 + tr[lane];
    float o1 = acc[0][1] * w0 + acc[1][1] * w1 + acc[2][1] * w2 + tr[32 + lane];
    float o2 = acc[0][2] * w0 + acc[1][2] * w1 + acc[2][2] * w2 + tr[64 + lane];
    float o3 = acc[0][3] * w0 + acc[1][3] * w1 + acc[2][3] * w2 + tr[96 + lane];

    long zb = (long)node * 128;
    z2[zb + lane] = o0;
    z2[zb + 32 + lane] = o1;
    z2[zb + 64 + lane] = o2;
    z2[zb + 96 + lane] = o3;

    atomicAdd(&ss[lane], o0);       atomicAdd(&sqs[lane], o0 * o0);
    atomicAdd(&ss[32 + lane], o1);  atomicAdd(&sqs[32 + lane], o1 * o1);
    atomicAdd(&ss[64 + lane], o2);  atomicAdd(&sqs[64 + lane], o2 * o2);
    atomicAdd(&ss[96 + lane], o3);  atomicAdd(&sqs[96 + lane], o3 * o3);
    __syncthreads();
    if (tid < 128) {
        atomicAdd(&sumP[tid], ss[tid]);
        atomicAdd(&sqP[tid], sqs[tid]);
    }
}

// ---------------- head with fused BN(mlp2) + BN(bn2) + relu ------------------
__global__ void k_final(const float* __restrict__ ow, const float* __restrict__ ob,
                        const float* __restrict__ scm, const float* __restrict__ shm,
                        const float* __restrict__ scg, const float* __restrict__ shg,
                        float* __restrict__ out) {
    int g = blockIdx.x * blockDim.x + threadIdx.x;
    int node = g >> 5;
    int lane = g & 31;
    if (node >= NN) return;
    float4 a  = *(const float4*)&g_zmlp[(long)node * 128 + lane * 4];
    float4 sm = *(const float4*)&scm[lane * 4];
    float4 hm = *(const float4*)&shm[lane * 4];
    float4 w1 = *(const float4*)&ow[lane * 4];
    float4 b  = *(const float4*)&g_agg2[(long)node * 128 + lane * 4];
    float4 sg = *(const float4*)&scg[lane * 4];
    float4 hg = *(const float4*)&shg[lane * 4];
    float4 w2 = *(const float4*)&ow[128 + lane * 4];
    float sum =
        fmaxf(fmaf(a.x, sm.x, hm.x), 0.f) * w1.x + fmaxf(fmaf(a.y, sm.y, hm.y), 0.f) * w1.y +
        fmaxf(fmaf(a.z, sm.z, hm.z), 0.f) * w1.z + fmaxf(fmaf(a.w, sm.w, hm.w), 0.f) * w1.w +
        fmaxf(fmaf(b.x, sg.x, hg.x), 0.f) * w2.x + fmaxf(fmaf(b.y, sg.y, hg.y), 0.f) * w2.y +
        fmaxf(fmaf(b.z, sg.z, hg.z), 0.f) * w2.z + fmaxf(fmaf(b.w, sg.w, hg.w), 0.f) * w2.w;
#pragma unroll
    for (int off = 16; off > 0; off >>= 1) sum += __shfl_down_sync(0xffffffffu, sum, off);
    if (lane == 0) out[node] = sum + ob[0];
}

// ---------------- host -------------------------------------------------------
extern "C" void kernel_launch(void* const* d_in, const int* in_sizes, int n_in,
                              void* d_out, int out_size) {
    const float* x       = (const float*)d_in[0];
    const float* hsd     = (const float*)d_in[1];
    const int*   ei      = (const int*)d_in[2];
    const int*   et      = (const int*)d_in[3];
    const float* mlp_w1  = (const float*)d_in[4];
    const float* mlp_b1  = (const float*)d_in[5];
    const float* mlp_g1  = (const float*)d_in[6];
    const float* mlp_be1 = (const float*)d_in[7];
    const float* mlp_w2  = (const float*)d_in[8];
    const float* mlp_b2  = (const float*)d_in[9];
    const float* mlp_g2  = (const float*)d_in[10];
    const float* mlp_be2 = (const float*)d_in[11];
    const float* rg1_wrel  = (const float*)d_in[12];
    const float* rg1_wroot = (const float*)d_in[13];
    const float* rg1_b     = (const float*)d_in[14];
    const float* bn1_g     = (const float*)d_in[15];
    const float* bn1_b     = (const float*)d_in[16];
    const float* rg2_wrel  = (const float*)d_in[17];
    const float* rg2_wroot = (const float*)d_in[18];
    const float* rg2_b     = (const float*)d_in[19];
    const float* bn2_g     = (const float*)d_in[20];
    const float* bn2_b     = (const float*)d_in[21];
    const float* out_w     = (const float*)d_in[22];
    const float* out_b     = (const float*)d_in[23];
    const int* src = ei;
    const int* dst = ei + EE;
    float* out = (float*)d_out;

    float *bufA, *A1, *zmlp, *t2, *agg1, *agg2, *wcat, *bias2, *sum, *sq;
    int *hist;
    cudaGetSymbolAddress((void**)&bufA, g_bufA);
    cudaGetSymbolAddress((void**)&A1, g_A1);
    cudaGetSymbolAddress((void**)&zmlp, g_zmlp);
    cudaGetSymbolAddress((void**)&t2, g_t2);
    cudaGetSymbolAddress((void**)&agg1, g_agg1);
    cudaGetSymbolAddress((void**)&agg2, g_agg2);
    cudaGetSymbolAddress((void**)&wcat, g_wcat);
    cudaGetSymbolAddress((void**)&bias2, g_bias2);
    cudaGetSymbolAddress((void**)&sum, g_sum);
    cudaGetSymbolAddress((void**)&sq, g_sq);
    cudaGetSymbolAddress((void**)&hist, g_hist);

    cudaFuncSetAttribute(sgemm_bias, cudaFuncAttributeMaxDynamicSharedMemorySize, SM_TOTAL);

    const int T = 256;
    float* wcat1 = wcat;
    float* wcat2 = wcat + 256 * 128;
    int nodeGrid = (NN * 32) / T;              // 12500, exact
    int gyAll = (NN + 127) / 128;              // 782

    cudaStream_t s0 = 0, sB;
    cudaStreamCreate(&sB);
    cudaEvent_t evFork, evG2, evJoin;
    cudaEventCreateWithFlags(&evFork, cudaEventDisableTiming);
    cudaEventCreateWithFlags(&evG2, cudaEventDisableTiming);
    cudaEventCreateWithFlags(&evJoin, cudaEventDisableTiming);

    // --- prologue on s0 ---
    k_zero_f2<<<4, T, 0, s0>>>(sum, sq, 1024);
    cudaEventRecord(evFork, s0);
    cudaStreamWaitEvent(sB, evFork, 0);

    // --- track B: CSR + weights + GNN chain ---
    k_zero_i<<<(NN + T - 1) / T, T, 0, sB>>>(hist, NN);
    k_prep_w<<<(3 * 128 * 128 + T - 1) / T, T, 0, sB>>>(rg1_wrel, rg1_wroot,
                                                        rg2_wrel, rg2_wroot, rg2_b);
    k_hist<<<(EE + T - 1) / T, T, 0, sB>>>(dst);
    k_scan1<<<NB1, 512, 0, sB>>>();
    k_scan2<<<1, 256, 0, sB>>>();
    k_scan3<<<NB1, 512, 0, sB>>>();
    k_place<<<(EE + T - 1) / T, T, 0, sB>>>(src, dst, et);
    k_asda<<<nodeGrid, T, 0, sB>>>(x, hsd);
    k_agg1<<<nodeGrid, T, 0, sB>>>();
    // rgcn1: z1 = A1 @ wcat1 + b (raw, stats fused)
    sgemm_bias<<<dim3(1, gyAll, 1), T, SM_TOTAL, sB>>>(A1, wcat1, rg1_b, agg1, NN, 256, 128, 256,
                                                       sum + 512, sq + 512, nullptr, nullptr);
    k_bnprep<<<1, 128, 0, sB>>>(sum + 512, sq + 512, bn1_g, bn1_b, 128);
    // t = BN(z1) @ wcat2' (+bias2 in root slot), BN1 fused into A-load
    sgemm_bias<<<dim3(4, gyAll, 1), T, SM_TOTAL, sB>>>(agg1, wcat2, bias2, t2, NN, 128, 512, 128,
                                                       nullptr, nullptr, sum + 512, sq + 512);
    cudaEventRecord(evG2, sB);
    k_gather2<<<nodeGrid, T, 0, sB>>>(t2, agg2, sum + 768, sq + 768);
    k_bnprep<<<1, 128, 0, sB>>>(sum + 768, sq + 768, bn2_g, bn2_b, 128);
    cudaEventRecord(evJoin, sB);

    // --- track A: MLP branch (mlp2 delayed to overlap gather2) ---
    sgemm_bias<<<dim3(2, gyAll, 1), T, SM_TOTAL, s0>>>(x, mlp_w1, mlp_b1, bufA, NN, 64, 256, 64,
                                                       sum + 0, sq + 0, nullptr, nullptr);
    k_bnprep<<<1, 256, 0, s0>>>(sum + 0, sq + 0, mlp_g1, mlp_be1, 256);
    cudaStreamWaitEvent(s0, evG2, 0);
    sgemm_bias<<<dim3(1, gyAll, 1), T, SM_TOTAL, s0>>>(bufA, mlp_w2, mlp_b2, zmlp, NN, 256, 128, 256,
                                                       sum + 256, sq + 256, sum + 0, sq + 0);
    k_bnprep<<<1, 128, 0, s0>>>(sum + 256, sq + 256, mlp_g2, mlp_be2, 128);

    // join + head
    cudaStreamWaitEvent(s0, evJoin, 0);
    k_final<<<(NN * 32) / T, T, 0, s0>>>(out_w, out_b,
                                         sum + 256, sq + 256,
                                         sum + 768, sq + 768, out);
}

// round 11
// speedup vs baseline: 1.0020x; 1.0020x over previous
#include <cuda_runtime.h>

#define NN 100000
#define EE 1600000
#define EPS 1e-5f
#define NB1 196        // ceil(NN/512)

// ---------------- scratch ---------------------------------------------------
__device__ float g_bufA[NN * 256];     // MLP hidden raw (track A only)
__device__ float g_A1[NN * 256];       // [agg_r0|agg_r1|agg_r2|h_in] (track B)
__device__ float g_zmlp[NN * 128];     // raw mlp2 output (BN fused into k_final)
__device__ float g_t2[(long)NN * 512]; // t = BN(z1) @ [Wr0|Wr1|Wr2|Wroot]
__device__ float g_agg1[NN * 128];     // raw rgcn1 output z1
__device__ float g_agg2[NN * 128];     // raw z2 (BN fused into k_final)
__device__ float g_wcat[256 * 128 + 128 * 512];
__device__ float g_bias2[512];
__device__ float g_sum[4 * 256];
__device__ float g_sq[4 * 256];
__device__ int   g_hist[NN];
__device__ int   g_row[NN];
__device__ int   g_cur[NN];
__device__ int   g_incl[NN];
__device__ int   g_bsum[256];
__device__ int   g_packed[EE];         // src | (rel<<20)

// ---------------- f32x2 helpers ---------------------------------------------
typedef unsigned long long ull;
__device__ __forceinline__ ull pack2(float v) {
    ull r;
    asm("mov.b64 %0, {%1, %1};" : "=l"(r) : "f"(v));
    return r;
}
__device__ __forceinline__ void fma2(ull& d, ull a, ull b) {
    asm("fma.rn.f32x2 %0, %1, %2, %0;" : "+l"(d) : "l"(a), "l"(b));
}
__device__ __forceinline__ float2 unpack2(ull v) {
    float2 f;
    asm("mov.b64 {%0, %1}, %2;" : "=f"(f.x), "=f"(f.y) : "l"(v));
    return f;
}

// ---------------- utility ---------------------------------------------------
__global__ void k_zero_i(int* p, int n) {
    int i = blockIdx.x * blockDim.x + threadIdx.x;
    if (i < n) p[i] = 0;
}
__global__ void k_zero_f2(float* p, float* q, int n) {
    int i = blockIdx.x * blockDim.x + threadIdx.x;
    if (i < n) { p[i] = 0.0f; q[i] = 0.0f; }
}

// stack weights: wcat1=(256,128)=[rg1_wrel;rg1_wroot], wcat2'=(128,512) cols [Wr0|Wr1|Wr2|Wroot]
__global__ void k_prep_w(const float* __restrict__ r1rel, const float* __restrict__ r1root,
                         const float* __restrict__ r2rel, const float* __restrict__ r2root,
                         const float* __restrict__ rg2b) {
    int i = blockIdx.x * blockDim.x + threadIdx.x;
    if (i < 3 * 64 * 128) g_wcat[i] = r1rel[i];
    else if (i < 4 * 64 * 128) g_wcat[i] = r1root[i - 3 * 64 * 128];
    if (i < 3 * 128 * 128) {
        int r = i >> 14;
        int rem = i & 16383;
        int k = rem >> 7, j = rem & 127;
        g_wcat[256 * 128 + k * 512 + r * 128 + j] = r2rel[i];
    }
    if (i < 128 * 128) {
        int k = i >> 7, j = i & 127;
        g_wcat[256 * 128 + k * 512 + 384 + j] = r2root[i];
    }
    if (i < 512) g_bias2[i] = (i >= 384) ? rg2b[i - 384] : 0.0f;
}

// ---------------- CSR build --------------------------------------------------
__global__ void k_hist(const int* __restrict__ dst) {
    int i = blockIdx.x * blockDim.x + threadIdx.x;
    if (i < EE) atomicAdd(&g_hist[dst[i]], 1);
}
__global__ void k_scan1() {
    __shared__ int sm[512];
    int i = blockIdx.x * 512 + threadIdx.x;
    int v = (i < NN) ? g_hist[i] : 0;
    sm[threadIdx.x] = v;
    __syncthreads();
    for (int off = 1; off < 512; off <<= 1) {
        int t = (threadIdx.x >= off) ? sm[threadIdx.x - off] : 0;
        __syncthreads();
        sm[threadIdx.x] += t;
        __syncthreads();
    }
    if (i < NN) g_incl[i] = sm[threadIdx.x];
    if (threadIdx.x == 511) g_bsum[blockIdx.x] = sm[511];
}
__global__ void k_scan2() {
    __shared__ int sm[256];
    int t = threadIdx.x;
    int v = (t < NB1) ? g_bsum[t] : 0;
    sm[t] = v;
    __syncthreads();
    for (int off = 1; off < 256; off <<= 1) {
        int u = (t >= off) ? sm[t - off] : 0;
        __syncthreads();
        sm[t] += u;
        __syncthreads();
    }
    if (t < NB1) g_bsum[t] = sm[t] - v;  // exclusive
}
__global__ void k_scan3() {
    int i = blockIdx.x * 512 + threadIdx.x;
    if (i >= NN) return;
    int r = g_incl[i] - g_hist[i] + g_bsum[blockIdx.x];
    g_row[i] = r;
    g_cur[i] = r;
}
__global__ void k_place(const int* __restrict__ src, const int* __restrict__ dst,
                        const int* __restrict__ et) {
    int i = blockIdx.x * blockDim.x + threadIdx.x;
    if (i >= EE) return;
    int pos = atomicAdd(&g_cur[dst[i]], 1);
    g_packed[pos] = src[i] | (et[i] << 20);
}

// ------- SGEMM (f32x2, double-buffered) + fused col-stats + fused A-side BN --
#define BM 128
#define BN 128
#define BKK 16
#define TM 8
#define TN 8
#define TN2 4

__global__ __launch_bounds__(256)
void sgemm_bias(const float* __restrict__ A, const float* __restrict__ B,
                const float* __restrict__ bias, float* __restrict__ C,
                int M, int K, int Nc, int lda,
                float* sumP, float* sqP,
                const float* __restrict__ aSc, const float* __restrict__ aSh) {
    __shared__ float As[2][BKK][BM];
    __shared__ float Bs[2][BKK][BN];
    __shared__ float csum[BN];
    __shared__ float csq[BN];

    int tid = threadIdx.x;
    int tcol = tid & 15;
    int trow = tid >> 4;
    int rowBase = blockIdx.y * 128;
    int colBase = blockIdx.x * 128;

    if (sumP && tid < BN) { csum[tid] = 0.0f; csq[tid] = 0.0f; }

    ull acc2[TM][TN2];
#pragma unroll
    for (int i = 0; i < TM; i++)
#pragma unroll
        for (int j = 0; j < TN2; j++) acc2[i][j] = 0ull;

    int aRow = tid >> 2, aCol4 = tid & 3;
    int bRow = tid >> 5, bCol4 = tid & 31;
    int grow0 = rowBase + aRow;
    int grow1 = rowBase + aRow + 64;

    float4 av0, av1, bv0, bv1;

    auto loadG = [&](int k0) {
        int kb = k0 + aCol4 * 4;
        av0 = make_float4(0.f, 0.f, 0.f, 0.f);
        av1 = av0;
        if (grow0 < M) {
            av0 = *(const float4*)&A[(long)grow0 * lda + kb];
            if (aSc) {
                av0.x = fmaxf(fmaf(av0.x, aSc[kb + 0], aSh[kb + 0]), 0.0f);
                av0.y = fmaxf(fmaf(av0.y, aSc[kb + 1], aSh[kb + 1]), 0.0f);
                av0.z = fmaxf(fmaf(av0.z, aSc[kb + 2], aSh[kb + 2]), 0.0f);
                av0.w = fmaxf(fmaf(av0.w, aSc[kb + 3], aSh[kb + 3]), 0.0f);
            }
        }
        if (grow1 < M) {
            av1 = *(const float4*)&A[(long)grow1 * lda + kb];
            if (aSc) {
                av1.x = fmaxf(fmaf(av1.x, aSc[kb + 0], aSh[kb + 0]), 0.0f);
                av1.y = fmaxf(fmaf(av1.y, aSc[kb + 1], aSh[kb + 1]), 0.0f);
                av1.z = fmaxf(fmaf(av1.z, aSc[kb + 2], aSh[kb + 2]), 0.0f);
                av1.w = fmaxf(fmaf(av1.w, aSc[kb + 3], aSh[kb + 3]), 0.0f);
            }
        }
        bv0 = *(const float4*)&B[(long)(k0 + bRow) * Nc + colBase + bCol4 * 4];
        bv1 = *(const float4*)&B[(long)(k0 + bRow + 8) * Nc + colBase + bCol4 * 4];
    };
    auto storeS = [&](int buf) {
        As[buf][aCol4 * 4 + 0][aRow] = av0.x;
        As[buf][aCol4 * 4 + 1][aRow] = av0.y;
        As[buf][aCol4 * 4 + 2][aRow] = av0.z;
        As[buf][aCol4 * 4 + 3][aRow] = av0.w;
        As[buf][aCol4 * 4 + 0][aRow + 64] = av1.x;
        As[buf][aCol4 * 4 + 1][aRow + 64] = av1.y;
        As[buf][aCol4 * 4 + 2][aRow + 64] = av1.z;
        As[buf][aCol4 * 4 + 3][aRow + 64] = av1.w;
        *(float4*)&Bs[buf][bRow][bCol4 * 4] = bv0;
        *(float4*)&Bs[buf][bRow + 8][bCol4 * 4] = bv1;
    };

    loadG(0);
    storeS(0);
    __syncthreads();

    int S = K / BKK;
    for (int s = 0; s < S; s++) {
        int cur = s & 1;
        if (s + 1 < S) loadG((s + 1) * BKK);
#pragma unroll
        for (int kk = 0; kk < BKK; kk++) {
            float ra[TM];
            ull rb2[TN2];
            *(float4*)&ra[0] = *(const float4*)&As[cur][kk][trow * TM];
            *(float4*)&ra[4] = *(const float4*)&As[cur][kk][trow * TM + 4];
            const ull* bp = (const ull*)&Bs[cur][kk][tcol * TN];
            rb2[0] = bp[0]; rb2[1] = bp[1]; rb2[2] = bp[2]; rb2[3] = bp[3];
#pragma unroll
            for (int i = 0; i < TM; i++) {
                ull a2 = pack2(ra[i]);
#pragma unroll
                for (int j = 0; j < TN2; j++) fma2(acc2[i][j], a2, rb2[j]);
            }
        }
        if (s + 1 < S) storeS((s + 1) & 1);
        __syncthreads();
    }

    // epilogue: bias, write, per-column partial stats
#pragma unroll
    for (int jp = 0; jp < TN2; jp++) {
        int col = colBase + tcol * TN + jp * 2;
        float bv0f = bias[col], bv1f = bias[col + 1];
        float s0 = 0.f, q0 = 0.f, s1 = 0.f, q1 = 0.f;
#pragma unroll
        for (int i = 0; i < TM; i++) {
            int grow = rowBase + trow * TM + i;
            if (grow < M) {
                float2 p = unpack2(acc2[i][jp]);
                p.x += bv0f; p.y += bv1f;
                *(float2*)&C[(long)grow * Nc + col] = p;
                s0 += p.x; q0 += p.x * p.x;
                s1 += p.y; q1 += p.y * p.y;
            }
        }
        if (sumP) {
            atomicAdd(&csum[tcol * TN + jp * 2], s0);
            atomicAdd(&csq[tcol * TN + jp * 2], q0);
            atomicAdd(&csum[tcol * TN + jp * 2 + 1], s1);
            atomicAdd(&csq[tcol * TN + jp * 2 + 1], q1);
        }
    }
    if (sumP) {
        __syncthreads();
        if (tid < BN) {
            atomicAdd(&sumP[colBase + tid], csum[tid]);
            atomicAdd(&sqP[colBase + tid], csq[tid]);
        }
    }
}

// ---------------- BN prep ----------------------------------------------------
__global__ void k_bnprep(float* sum, float* sq, const float* __restrict__ g,
                         const float* __restrict__ b, int C) {
    int c = threadIdx.x;
    if (c >= C) return;
    const float invN = 1.0f / (float)NN;
    float m = sum[c] * invN;
    float var = sq[c] * invN - m * m;
    float sc = g[c] * rsqrtf(var + EPS);
    float sh = b[c] - m * sc;
    sum[c] = sc;
    sq[c] = sh;
}

// ---------------- ASDA (CSR, warp per node) ---------------------------------
__global__ __launch_bounds__(256)
void k_asda(const float* __restrict__ x, const float* __restrict__ hsd) {
    int node = (blockIdx.x * blockDim.x + threadIdx.x) >> 5;
    int lane = threadIdx.x & 31;
    if (node >= NN) return;
    int start = g_row[node];
    int end = start + g_hist[node];
    float hd = hsd[node];

    float den = 0.f;
    for (int base = start; base < end; base += 32) {
        int idx = base + lane;
        float e = 0.f;
        if (idx < end) {
            int s = g_packed[idx] & 0xFFFFF;
            e = __expf((hsd[s] - hd) * 10.0f);
        }
        den += e;
    }
#pragma unroll
    for (int o = 16; o > 0; o >>= 1) den += __shfl_xor_sync(0xffffffffu, den, o);
    float inv = 1.0f / fmaxf(den, 1e-9f);

    float a0 = x[(long)node * 64 + lane];
    float a1 = x[(long)node * 64 + 32 + lane];
    for (int base = start; base < end; base += 32) {
        int idx = base + lane;
        int v = 0;
        float al = 0.f;
        if (idx < end) {
            v = g_packed[idx];
            int s = v & 0xFFFFF;
            al = __expf((hsd[s] - hd) * 10.0f) * inv;
        }
        int m = min(32, end - base);
        for (int j = 0; j < m; j++) {
            int vv = __shfl_sync(0xffffffffu, v, j);
            float aa = __shfl_sync(0xffffffffu, al, j);
            int s = vv & 0xFFFFF;
            a0 = fmaf(aa, x[(long)s * 64 + lane], a0);
            a1 = fmaf(aa, x[(long)s * 64 + 32 + lane], a1);
        }
    }
    g_A1[(long)node * 256 + 192 + lane] = a0;
    g_A1[(long)node * 256 + 224 + lane] = a1;
}

// ---------------- RGCN layer-1 input aggregation (dim 64) --------------------
__global__ __launch_bounds__(256)
void k_agg1() {
    int node = (blockIdx.x * blockDim.x + threadIdx.x) >> 5;
    int lane = threadIdx.x & 31;
    if (node >= NN) return;
    int start = g_row[node];
    int end = start + g_hist[node];

    float a00 = 0, a01 = 0, a10 = 0, a11 = 0, a20 = 0, a21 = 0;
    int c0 = 0, c1 = 0, c2 = 0;
    for (int base = start; base < end; base += 32) {
        int idx = base + lane;
        int v = (idx < end) ? g_packed[idx] : 0;
        int m = min(32, end - base);
        for (int j = 0; j < m; j++) {
            int vv = __shfl_sync(0xffffffffu, v, j);
            int s = vv & 0xFFFFF;
            int r = vv >> 20;
            float f0 = g_A1[(long)s * 256 + 192 + lane];
            float f1 = g_A1[(long)s * 256 + 224 + lane];
            if (r == 0)      { a00 += f0; a01 += f1; c0++; }
            else if (r == 1) { a10 += f0; a11 += f1; c1++; }
            else             { a20 += f0; a21 += f1; c2++; }
        }
    }
    float w0 = 1.0f / (float)max(c0, 1);
    float w1 = 1.0f / (float)max(c1, 1);
    float w2 = 1.0f / (float)max(c2, 1);
    long b = (long)node * 256;
    g_A1[b + 0 + lane] = a00 * w0;  g_A1[b + 32 + lane] = a01 * w0;
    g_A1[b + 64 + lane] = a10 * w1; g_A1[b + 96 + lane] = a11 * w1;
    g_A1[b + 128 + lane] = a20 * w2; g_A1[b + 160 + lane] = a21 * w2;
}

// ------- layer-2: single-pass gather of t, assemble z2, fused BN2 stats ------
__global__ __launch_bounds__(256)
void k_gather2(const float* __restrict__ t, float* __restrict__ z2,
               float* sumP, float* sqP) {
    __shared__ float ss[128];
    __shared__ float sqs[128];
    int tid = threadIdx.x;
    if (tid < 128) { ss[tid] = 0.0f; sqs[tid] = 0.0f; }
    __syncthreads();

    int node = (blockIdx.x * blockDim.x + tid) >> 5;   // grid exact
    int lane = tid & 31;
    int start = g_row[node];
    int end = start + g_hist[node];

    float acc[3][4] = {};
    int cnt[3] = {0, 0, 0};
    for (int base = start; base < end; base += 32) {
        int idx = base + lane;
        int v = (idx < end) ? g_packed[idx] : 0;
        int m = min(32, end - base);
        for (int j = 0; j < m; j++) {
            int vv = __shfl_sync(0xffffffffu, v, j);
            int s = vv & 0xFFFFF;
            int r = vv >> 20;
            const float* tp = t + (long)s * 512 + r * 128;
            float f0 = tp[lane], f1 = tp[32 + lane], f2 = tp[64 + lane], f3 = tp[96 + lane];
            if (r == 0)      { acc[0][0] += f0; acc[0][1] += f1; acc[0][2] += f2; acc[0][3] += f3; cnt[0]++; }
            else if (r == 1) { acc[1][0] += f0; acc[1][1] += f1; acc[1][2] += f2; acc[1][3] += f3; cnt[1]++; }
            else             { acc[2][0] += f0; acc[2][1] += f1; acc[2][2] += f2; acc[2][3] += f3; cnt[2]++; }
        }
    }
    float w0 = 1.0f / (float)max(cnt[0], 1);
    float w1 = 1.0f / (float)max(cnt[1], 1);
    float w2 = 1.0f / (float)max(cnt[2], 1);
    const float* tr = t + (long)node * 512 + 384;
    float o0 = acc[0][0] * w0 + acc[1][0] * w1 + acc[2][0] * w2 + tr[lane];
    float o1 = acc[0][1] * w0 + acc[1][1] * w1 + acc[2][1] * w2 + tr[32 + lane];
    float o2 = acc[0][2] * w0 + acc[1][2] * w1 + acc[2][2] * w2 + tr[64 + lane];
    float o3 = acc[0][3] * w0 + acc[1][3] * w1 + acc[2][3] * w2 + tr[96 + lane];

    long zb = (long)node * 128;
    z2[zb + lane] = o0;
    z2[zb + 32 + lane] = o1;
    z2[zb + 64 + lane] = o2;
    z2[zb + 96 + lane] = o3;

    atomicAdd(&ss[lane], o0);       atomicAdd(&sqs[lane], o0 * o0);
    atomicAdd(&ss[32 + lane], o1);  atomicAdd(&sqs[32 + lane], o1 * o1);
    atomicAdd(&ss[64 + lane], o2);  atomicAdd(&sqs[64 + lane], o2 * o2);
    atomicAdd(&ss[96 + lane], o3);  atomicAdd(&sqs[96 + lane], o3 * o3);
    __syncthreads();
    if (tid < 128) {
        atomicAdd(&sumP[tid], ss[tid]);
        atomicAdd(&sqP[tid], sqs[tid]);
    }
}

// ---------------- head with fused BN(mlp2) + BN(bn2) + relu ------------------
__global__ void k_final(const float* __restrict__ ow, const float* __restrict__ ob,
                        const float* __restrict__ scm, const float* __restrict__ shm,
                        const float* __restrict__ scg, const float* __restrict__ shg,
                        float* __restrict__ out) {
    int g = blockIdx.x * blockDim.x + threadIdx.x;
    int node = g >> 5;
    int lane = g & 31;
    if (node >= NN) return;
    float4 a  = *(const float4*)&g_zmlp[(long)node * 128 + lane * 4];
    float4 sm = *(const float4*)&scm[lane * 4];
    float4 hm = *(const float4*)&shm[lane * 4];
    float4 w1 = *(const float4*)&ow[lane * 4];
    float4 b  = *(const float4*)&g_agg2[(long)node * 128 + lane * 4];
    float4 sg = *(const float4*)&scg[lane * 4];
    float4 hg = *(const float4*)&shg[lane * 4];
    float4 w2 = *(const float4*)&ow[128 + lane * 4];
    float sum =
        fmaxf(fmaf(a.x, sm.x, hm.x), 0.f) * w1.x + fmaxf(fmaf(a.y, sm.y, hm.y), 0.f) * w1.y +
        fmaxf(fmaf(a.z, sm.z, hm.z), 0.f) * w1.z + fmaxf(fmaf(a.w, sm.w, hm.w), 0.f) * w1.w +
        fmaxf(fmaf(b.x, sg.x, hg.x), 0.f) * w2.x + fmaxf(fmaf(b.y, sg.y, hg.y), 0.f) * w2.y +
        fmaxf(fmaf(b.z, sg.z, hg.z), 0.f) * w2.z + fmaxf(fmaf(b.w, sg.w, hg.w), 0.f) * w2.w;
#pragma unroll
    for (int off = 16; off > 0; off >>= 1) sum += __shfl_down_sync(0xffffffffu, sum, off);
    if (lane == 0) out[node] = sum + ob[0];
}

// ---------------- host -------------------------------------------------------
extern "C" void kernel_launch(void* const* d_in, const int* in_sizes, int n_in,
                              void* d_out, int out_size) {
    const float* x       = (const float*)d_in[0];
    const float* hsd     = (const float*)d_in[1];
    const int*   ei      = (const int*)d_in[2];
    const int*   et      = (const int*)d_in[3];
    const float* mlp_w1  = (const float*)d_in[4];
    const float* mlp_b1  = (const float*)d_in[5];
    const float* mlp_g1  = (const float*)d_in[6];
    const float* mlp_be1 = (const float*)d_in[7];
    const float* mlp_w2  = (const float*)d_in[8];
    const float* mlp_b2  = (const float*)d_in[9];
    const float* mlp_g2  = (const float*)d_in[10];
    const float* mlp_be2 = (const float*)d_in[11];
    const float* rg1_wrel  = (const float*)d_in[12];
    const float* rg1_wroot = (const float*)d_in[13];
    const float* rg1_b     = (const float*)d_in[14];
    const float* bn1_g     = (const float*)d_in[15];
    const float* bn1_b     = (const float*)d_in[16];
    const float* rg2_wrel  = (const float*)d_in[17];
    const float* rg2_wroot = (const float*)d_in[18];
    const float* rg2_b     = (const float*)d_in[19];
    const float* bn2_g     = (const float*)d_in[20];
    const float* bn2_b     = (const float*)d_in[21];
    const float* out_w     = (const float*)d_in[22];
    const float* out_b     = (const float*)d_in[23];
    const int* src = ei;
    const int* dst = ei + EE;
    float* out = (float*)d_out;

    float *bufA, *A1, *zmlp, *t2, *agg1, *agg2, *wcat, *bias2, *sum, *sq;
    int *hist;
    cudaGetSymbolAddress((void**)&bufA, g_bufA);
    cudaGetSymbolAddress((void**)&A1, g_A1);
    cudaGetSymbolAddress((void**)&zmlp, g_zmlp);
    cudaGetSymbolAddress((void**)&t2, g_t2);
    cudaGetSymbolAddress((void**)&agg1, g_agg1);
    cudaGetSymbolAddress((void**)&agg2, g_agg2);
    cudaGetSymbolAddress((void**)&wcat, g_wcat);
    cudaGetSymbolAddress((void**)&bias2, g_bias2);
    cudaGetSymbolAddress((void**)&sum, g_sum);
    cudaGetSymbolAddress((void**)&sq, g_sq);
    cudaGetSymbolAddress((void**)&hist, g_hist);

    const int T = 256;
    float* wcat1 = wcat;
    float* wcat2 = wcat + 256 * 128;
    int nodeGrid = (NN * 32) / T;              // 12500, exact
    int gyAll = (NN + BM - 1) / BM;            // 782

    cudaStream_t s0 = 0, sB;
    cudaStreamCreate(&sB);
    cudaEvent_t evFork, evJoin;
    cudaEventCreateWithFlags(&evFork, cudaEventDisableTiming);
    cudaEventCreateWithFlags(&evJoin, cudaEventDisableTiming);

    // --- prologue on s0 ---
    k_zero_f2<<<4, T, 0, s0>>>(sum, sq, 1024);
    cudaEventRecord(evFork, s0);
    cudaStreamWaitEvent(sB, evFork, 0);

    // --- track B: CSR + weights + GNN chain ---
    k_zero_i<<<(NN + T - 1) / T, T, 0, sB>>>(hist, NN);
    k_prep_w<<<(3 * 128 * 128 + T - 1) / T, T, 0, sB>>>(rg1_wrel, rg1_wroot,
                                                        rg2_wrel, rg2_wroot, rg2_b);
    k_hist<<<(EE + T - 1) / T, T, 0, sB>>>(dst);
    k_scan1<<<NB1, 512, 0, sB>>>();
    k_scan2<<<1, 256, 0, sB>>>();
    k_scan3<<<NB1, 512, 0, sB>>>();
    k_place<<<(EE + T - 1) / T, T, 0, sB>>>(src, dst, et);
    k_asda<<<nodeGrid, T, 0, sB>>>(x, hsd);
    k_agg1<<<nodeGrid, T, 0, sB>>>();
    // rgcn1: z1 = A1 @ wcat1 + b (raw, stats fused)
    sgemm_bias<<<dim3(1, gyAll, 1), T, 0, sB>>>(A1, wcat1, rg1_b, agg1, NN, 256, 128, 256,
                                                sum + 512, sq + 512, nullptr, nullptr);
    k_bnprep<<<1, 128, 0, sB>>>(sum + 512, sq + 512, bn1_g, bn1_b, 128);
    // t = BN(z1) @ wcat2' (+bias2 in root slot), BN1 fused into A-load
    sgemm_bias<<<dim3(4, gyAll, 1), T, 0, sB>>>(agg1, wcat2, bias2, t2, NN, 128, 512, 128,
                                                nullptr, nullptr, sum + 512, sq + 512);
    k_gather2<<<nodeGrid, T, 0, sB>>>(t2, agg2, sum + 768, sq + 768);
    k_bnprep<<<1, 128, 0, sB>>>(sum + 768, sq + 768, bn2_g, bn2_b, 128);
    cudaEventRecord(evJoin, sB);

    // --- track A: full MLP branch immediately (hidden under B's edge phase) ---
    sgemm_bias<<<dim3(2, gyAll, 1), T, 0, s0>>>(x, mlp_w1, mlp_b1, bufA, NN, 64, 256, 64,
                                                sum + 0, sq + 0, nullptr, nullptr);
    k_bnprep<<<1, 256, 0, s0>>>(sum + 0, sq + 0, mlp_g1, mlp_be1, 256);
    sgemm_bias<<<dim3(1, gyAll, 1), T, 0, s0>>>(bufA, mlp_w2, mlp_b2, zmlp, NN, 256, 128, 256,
                                                sum + 256, sq + 256, sum + 0, sq + 0);
    k_bnprep<<<1, 128, 0, s0>>>(sum + 256, sq + 256, mlp_g2, mlp_be2, 128);

    // join + head
    cudaStreamWaitEvent(s0, evJoin, 0);
    k_final<<<(NN * 32) / T, T, 0, s0>>>(out_w, out_b,
                                         sum + 256, sq + 256,
                                         sum + 768, sq + 768, out);
}

// round 12
// speedup vs baseline: 1.0648x; 1.0627x over previous
#include <cuda_runtime.h>

#define NN 100000
#define EE 1600000
#define EPS 1e-5f
#define NB1 196        // ceil(NN/512)

// ---------------- scratch ---------------------------------------------------
__device__ float g_bufA[NN * 256];     // MLP hidden raw (track A only)
__device__ float g_A1[NN * 256];       // [agg_r0|agg_r1|agg_r2|h_in] (track B)
__device__ float g_zmlp[NN * 128];     // raw mlp2 output (BN inlined in k_final)
__device__ float g_A2[(long)NN * 512]; // [agg_r0|agg_r1|agg_r2|z1'] for layer-2 GEMM
__device__ float g_agg1[NN * 128];     // raw rgcn1 output z1
__device__ float g_agg2[NN * 128];     // raw z2 (BN inlined in k_final)
__device__ float g_wcat[256 * 128 + 512 * 128];
__device__ float g_sum[4 * 256];
__device__ float g_sq[4 * 256];
__device__ float g_e[EE];              // cached per-edge exp
__device__ int   g_hist[NN];
__device__ int   g_row[NN];
__device__ int   g_cur[NN];
__device__ int   g_incl[NN];
__device__ int   g_bsum[256];
__device__ int   g_packed[EE];         // src | (rel<<20)

// ---------------- f32x2 helpers ---------------------------------------------
typedef unsigned long long ull;
__device__ __forceinline__ ull pack2(float v) {
    ull r;
    asm("mov.b64 %0, {%1, %1};" : "=l"(r) : "f"(v));
    return r;
}
__device__ __forceinline__ void fma2(ull& d, ull a, ull b) {
    asm("fma.rn.f32x2 %0, %1, %2, %0;" : "+l"(d) : "l"(a), "l"(b));
}
__device__ __forceinline__ float2 unpack2(ull v) {
    float2 f;
    asm("mov.b64 {%0, %1}, %2;" : "=f"(f.x), "=f"(f.y) : "l"(v));
    return f;
}

// ---------------- utility ---------------------------------------------------
__global__ void k_zero_i(int* p, int n) {
    int i = blockIdx.x * blockDim.x + threadIdx.x;
    if (i < n) p[i] = 0;
}
__global__ void k_zero_f2(float* p, float* q, int n) {
    int i = blockIdx.x * blockDim.x + threadIdx.x;
    if (i < n) { p[i] = 0.0f; q[i] = 0.0f; }
}
// stack [rg1_wrel | rg1_wroot] (256,128) and [rg2_wrel ; rg2_wroot] (512,128)
__global__ void k_prep_w(const float* __restrict__ r1rel, const float* __restrict__ r1root,
                         const float* __restrict__ r2rel, const float* __restrict__ r2root) {
    int i = blockIdx.x * blockDim.x + threadIdx.x;
    if (i < 3 * 64 * 128) g_wcat[i] = r1rel[i];
    else if (i < 4 * 64 * 128) g_wcat[i] = r1root[i - 3 * 64 * 128];
    if (i < 3 * 128 * 128) g_wcat[256 * 128 + i] = r2rel[i];
    else if (i < 4 * 128 * 128) g_wcat[256 * 128 + i] = r2root[i - 3 * 128 * 128];
}

// ---------------- CSR build --------------------------------------------------
__global__ void k_hist(const int* __restrict__ dst) {
    int i = blockIdx.x * blockDim.x + threadIdx.x;
    if (i < EE) atomicAdd(&g_hist[dst[i]], 1);
}
__global__ void k_scan1() {
    __shared__ int sm[512];
    int i = blockIdx.x * 512 + threadIdx.x;
    int v = (i < NN) ? g_hist[i] : 0;
    sm[threadIdx.x] = v;
    __syncthreads();
    for (int off = 1; off < 512; off <<= 1) {
        int t = (threadIdx.x >= off) ? sm[threadIdx.x - off] : 0;
        __syncthreads();
        sm[threadIdx.x] += t;
        __syncthreads();
    }
    if (i < NN) g_incl[i] = sm[threadIdx.x];
    if (threadIdx.x == 511) g_bsum[blockIdx.x] = sm[511];
}
__global__ void k_scan2() {
    __shared__ int sm[256];
    int t = threadIdx.x;
    int v = (t < NB1) ? g_bsum[t] : 0;
    sm[t] = v;
    __syncthreads();
    for (int off = 1; off < 256; off <<= 1) {
        int u = (t >= off) ? sm[t - off] : 0;
        __syncthreads();
        sm[t] += u;
        __syncthreads();
    }
    if (t < NB1) g_bsum[t] = sm[t] - v;  // exclusive
}
__global__ void k_scan3() {
    int i = blockIdx.x * 512 + threadIdx.x;
    if (i >= NN) return;
    int r = g_incl[i] - g_hist[i] + g_bsum[blockIdx.x];
    g_row[i] = r;
    g_cur[i] = r;
}
__global__ void k_place(const int* __restrict__ src, const int* __restrict__ dst,
                        const int* __restrict__ et) {
    int i = blockIdx.x * blockDim.x + threadIdx.x;
    if (i >= EE) return;
    int pos = atomicAdd(&g_cur[dst[i]], 1);
    g_packed[pos] = src[i] | (et[i] << 20);
}

// ------- SGEMM (f32x2, double-buffered) + fused col-stats + fused A-side BN --
#define BM 128
#define BN 128
#define BKK 16
#define TM 8
#define TN 8
#define TN2 4

__global__ __launch_bounds__(256)
void sgemm_bias(const float* __restrict__ A, const float* __restrict__ B,
                const float* __restrict__ bias, float* __restrict__ C,
                int M, int K, int Nc, int lda,
                float* sumP, float* sqP,
                const float* __restrict__ aSc, const float* __restrict__ aSh) {
    __shared__ float As[2][BKK][BM];
    __shared__ float Bs[2][BKK][BN];
    __shared__ float csum[BN];
    __shared__ float csq[BN];

    int tid = threadIdx.x;
    int tcol = tid & 15;
    int trow = tid >> 4;
    int rowBase = blockIdx.y * 128;
    int colBase = blockIdx.x * 128;

    if (sumP && tid < BN) { csum[tid] = 0.0f; csq[tid] = 0.0f; }

    ull acc2[TM][TN2];
#pragma unroll
    for (int i = 0; i < TM; i++)
#pragma unroll
        for (int j = 0; j < TN2; j++) acc2[i][j] = 0ull;

    int aRow = tid >> 2, aCol4 = tid & 3;
    int bRow = tid >> 5, bCol4 = tid & 31;
    int grow0 = rowBase + aRow;
    int grow1 = rowBase + aRow + 64;

    float4 av0, av1, bv0, bv1;

    auto loadG = [&](int k0) {
        int kb = k0 + aCol4 * 4;
        av0 = make_float4(0.f, 0.f, 0.f, 0.f);
        av1 = av0;
        if (grow0 < M) {
            av0 = *(const float4*)&A[(long)grow0 * lda + kb];
            if (aSc) {
                av0.x = fmaxf(fmaf(av0.x, aSc[kb + 0], aSh[kb + 0]), 0.0f);
                av0.y = fmaxf(fmaf(av0.y, aSc[kb + 1], aSh[kb + 1]), 0.0f);
                av0.z = fmaxf(fmaf(av0.z, aSc[kb + 2], aSh[kb + 2]), 0.0f);
                av0.w = fmaxf(fmaf(av0.w, aSc[kb + 3], aSh[kb + 3]), 0.0f);
            }
        }
        if (grow1 < M) {
            av1 = *(const float4*)&A[(long)grow1 * lda + kb];
            if (aSc) {
                av1.x = fmaxf(fmaf(av1.x, aSc[kb + 0], aSh[kb + 0]), 0.0f);
                av1.y = fmaxf(fmaf(av1.y, aSc[kb + 1], aSh[kb + 1]), 0.0f);
                av1.z = fmaxf(fmaf(av1.z, aSc[kb + 2], aSh[kb + 2]), 0.0f);
                av1.w = fmaxf(fmaf(av1.w, aSc[kb + 3], aSh[kb + 3]), 0.0f);
            }
        }
        bv0 = *(const float4*)&B[(long)(k0 + bRow) * Nc + colBase + bCol4 * 4];
        bv1 = *(const float4*)&B[(long)(k0 + bRow + 8) * Nc + colBase + bCol4 * 4];
    };
    auto storeS = [&](int buf) {
        As[buf][aCol4 * 4 + 0][aRow] = av0.x;
        As[buf][aCol4 * 4 + 1][aRow] = av0.y;
        As[buf][aCol4 * 4 + 2][aRow] = av0.z;
        As[buf][aCol4 * 4 + 3][aRow] = av0.w;
        As[buf][aCol4 * 4 + 0][aRow + 64] = av1.x;
        As[buf][aCol4 * 4 + 1][aRow + 64] = av1.y;
        As[buf][aCol4 * 4 + 2][aRow + 64] = av1.z;
        As[buf][aCol4 * 4 + 3][aRow + 64] = av1.w;
        *(float4*)&Bs[buf][bRow][bCol4 * 4] = bv0;
        *(float4*)&Bs[buf][bRow + 8][bCol4 * 4] = bv1;
    };

    loadG(0);
    storeS(0);
    __syncthreads();

    int S = K / BKK;
    for (int s = 0; s < S; s++) {
        int cur = s & 1;
        if (s + 1 < S) loadG((s + 1) * BKK);
#pragma unroll
        for (int kk = 0; kk < BKK; kk++) {
            float ra[TM];
            ull rb2[TN2];
            *(float4*)&ra[0] = *(const float4*)&As[cur][kk][trow * TM];
            *(float4*)&ra[4] = *(const float4*)&As[cur][kk][trow * TM + 4];
            const ull* bp = (const ull*)&Bs[cur][kk][tcol * TN];
            rb2[0] = bp[0]; rb2[1] = bp[1]; rb2[2] = bp[2]; rb2[3] = bp[3];
#pragma unroll
            for (int i = 0; i < TM; i++) {
                ull a2 = pack2(ra[i]);
#pragma unroll
                for (int j = 0; j < TN2; j++) fma2(acc2[i][j], a2, rb2[j]);
            }
        }
        if (s + 1 < S) storeS((s + 1) & 1);
        __syncthreads();
    }

    // epilogue: bias, write, per-column partial stats
#pragma unroll
    for (int jp = 0; jp < TN2; jp++) {
        int col = colBase + tcol * TN + jp * 2;
        float bv0f = bias[col], bv1f = bias[col + 1];
        float s0 = 0.f, q0 = 0.f, s1 = 0.f, q1 = 0.f;
#pragma unroll
        for (int i = 0; i < TM; i++) {
            int grow = rowBase + trow * TM + i;
            if (grow < M) {
                float2 p = unpack2(acc2[i][jp]);
                p.x += bv0f; p.y += bv1f;
                *(float2*)&C[(long)grow * Nc + col] = p;
                s0 += p.x; q0 += p.x * p.x;
                s1 += p.y; q1 += p.y * p.y;
            }
        }
        if (sumP) {
            atomicAdd(&csum[tcol * TN + jp * 2], s0);
            atomicAdd(&csq[tcol * TN + jp * 2], q0);
            atomicAdd(&csum[tcol * TN + jp * 2 + 1], s1);
            atomicAdd(&csq[tcol * TN + jp * 2 + 1], q1);
        }
    }
    if (sumP) {
        __syncthreads();
        if (tid < BN) {
            atomicAdd(&sumP[colBase + tid], csum[tid]);
            atomicAdd(&sqP[colBase + tid], csq[tid]);
        }
    }
}

// ---------------- BN prep (only used for mlp1, track A) ----------------------
__global__ void k_bnprep(float* sum, float* sq, const float* __restrict__ g,
                         const float* __restrict__ b, int C) {
    int c = threadIdx.x;
    if (c >= C) return;
    const float invN = 1.0f / (float)NN;
    float m = sum[c] * invN;
    float var = sq[c] * invN - m * m;
    float sc = g[c] * rsqrtf(var + EPS);
    float sh = b[c] - m * sc;
    sum[c] = sc;
    sq[c] = sh;
}

// ---------------- ASDA (CSR, warp per node, cached exp) ----------------------
__global__ __launch_bounds__(256)
void k_asda(const float* __restrict__ x, const float* __restrict__ hsd) {
    int node = (blockIdx.x * blockDim.x + threadIdx.x) >> 5;
    int lane = threadIdx.x & 31;
    if (node >= NN) return;
    int start = g_row[node];
    int end = start + g_hist[node];
    float hd = hsd[node];

    float den = 0.f;
    for (int base = start; base < end; base += 32) {
        int idx = base + lane;
        float e = 0.f;
        if (idx < end) {
            int s = g_packed[idx] & 0xFFFFF;
            e = __expf((hsd[s] - hd) * 10.0f);
            g_e[idx] = e;
        }
        den += e;
    }
#pragma unroll
    for (int o = 16; o > 0; o >>= 1) den += __shfl_xor_sync(0xffffffffu, den, o);
    float inv = 1.0f / fmaxf(den, 1e-9f);

    float a0 = x[(long)node * 64 + lane];
    float a1 = x[(long)node * 64 + 32 + lane];
    for (int base = start; base < end; base += 32) {
        int idx = base + lane;
        int v = 0;
        float al = 0.f;
        if (idx < end) {
            v = g_packed[idx];
            al = g_e[idx] * inv;
        }
        int m = min(32, end - base);
        for (int j = 0; j < m; j++) {
            int vv = __shfl_sync(0xffffffffu, v, j);
            float aa = __shfl_sync(0xffffffffu, al, j);
            int s = vv & 0xFFFFF;
            a0 = fmaf(aa, x[(long)s * 64 + lane], a0);
            a1 = fmaf(aa, x[(long)s * 64 + 32 + lane], a1);
        }
    }
    g_A1[(long)node * 256 + 192 + lane] = a0;
    g_A1[(long)node * 256 + 224 + lane] = a1;
}

// ---------------- RGCN layer-1 input aggregation (dim 64) --------------------
__global__ __launch_bounds__(256)
void k_agg1() {
    int node = (blockIdx.x * blockDim.x + threadIdx.x) >> 5;
    int lane = threadIdx.x & 31;
    if (node >= NN) return;
    int start = g_row[node];
    int end = start + g_hist[node];

    float a00 = 0, a01 = 0, a10 = 0, a11 = 0, a20 = 0, a21 = 0;
    int c0 = 0, c1 = 0, c2 = 0;
    for (int base = start; base < end; base += 32) {
        int idx = base + lane;
        int v = (idx < end) ? g_packed[idx] : 0;
        int m = min(32, end - base);
        for (int j = 0; j < m; j++) {
            int vv = __shfl_sync(0xffffffffu, v, j);
            int s = vv & 0xFFFFF;
            int r = vv >> 20;
            float f0 = g_A1[(long)s * 256 + 192 + lane];
            float f1 = g_A1[(long)s * 256 + 224 + lane];
            if (r == 0)      { a00 += f0; a01 += f1; c0++; }
            else if (r == 1) { a10 += f0; a11 += f1; c1++; }
            else             { a20 += f0; a21 += f1; c2++; }
        }
    }
    float w0 = 1.0f / (float)max(c0, 1);
    float w1 = 1.0f / (float)max(c1, 1);
    float w2 = 1.0f / (float)max(c2, 1);
    long b = (long)node * 256;
    g_A1[b + 0 + lane] = a00 * w0;  g_A1[b + 32 + lane] = a01 * w0;
    g_A1[b + 64 + lane] = a10 * w1; g_A1[b + 96 + lane] = a11 * w1;
    g_A1[b + 128 + lane] = a20 * w2; g_A1[b + 160 + lane] = a21 * w2;
}

// ------- layer-2 aggregation: build A2 = [aggs|z1'], BN1 prepped inline ------
__global__ __launch_bounds__(256)
void k_agg2(const float* __restrict__ z1, float* __restrict__ A2,
            const float* __restrict__ sumRaw, const float* __restrict__ sqRaw,
            const float* __restrict__ bg, const float* __restrict__ bb) {
    __shared__ float sc[128], sh[128];
    int tid = threadIdx.x;
    if (tid < 128) {
        const float invN = 1.0f / (float)NN;
        float m = sumRaw[tid] * invN;
        float var = sqRaw[tid] * invN - m * m;
        float s = bg[tid] * rsqrtf(var + EPS);
        sc[tid] = s;
        sh[tid] = bb[tid] - m * s;
    }
    __syncthreads();

    int node = (blockIdx.x * blockDim.x + tid) >> 5;   // grid exact
    int lane = tid & 31;
    int start = g_row[node];
    int end = start + g_hist[node];

    float sc0 = sc[lane], sc1 = sc[lane + 32], sc2 = sc[lane + 64], sc3 = sc[lane + 96];
    float sh0 = sh[lane], sh1 = sh[lane + 32], sh2 = sh[lane + 64], sh3 = sh[lane + 96];

    float acc[3][4] = {};
    int cnt[3] = {0, 0, 0};
    for (int base = start; base < end; base += 32) {
        int idx = base + lane;
        int v = (idx < end) ? g_packed[idx] : 0;
        int m = min(32, end - base);
        for (int j = 0; j < m; j++) {
            int vv = __shfl_sync(0xffffffffu, v, j);
            int s = vv & 0xFFFFF;
            int r = vv >> 20;
            long sb = (long)s * 128;
            float f0 = fmaxf(fmaf(z1[sb + lane],      sc0, sh0), 0.0f);
            float f1 = fmaxf(fmaf(z1[sb + 32 + lane], sc1, sh1), 0.0f);
            float f2 = fmaxf(fmaf(z1[sb + 64 + lane], sc2, sh2), 0.0f);
            float f3 = fmaxf(fmaf(z1[sb + 96 + lane], sc3, sh3), 0.0f);
            if (r == 0)      { acc[0][0] += f0; acc[0][1] += f1; acc[0][2] += f2; acc[0][3] += f3; cnt[0]++; }
            else if (r == 1) { acc[1][0] += f0; acc[1][1] += f1; acc[1][2] += f2; acc[1][3] += f3; cnt[1]++; }
            else             { acc[2][0] += f0; acc[2][1] += f1; acc[2][2] += f2; acc[2][3] += f3; cnt[2]++; }
        }
    }
    long b = (long)node * 512;
#pragma unroll
    for (int r = 0; r < 3; r++) {
        float w = 1.0f / (float)max(cnt[r], 1);
#pragma unroll
        for (int k = 0; k < 4; k++)
            A2[b + r * 128 + k * 32 + lane] = acc[r][k] * w;
    }
    long zb = (long)node * 128;
    A2[b + 384 + lane]      = fmaxf(fmaf(z1[zb + lane],      sc0, sh0), 0.0f);
    A2[b + 384 + 32 + lane] = fmaxf(fmaf(z1[zb + 32 + lane], sc1, sh1), 0.0f);
    A2[b + 384 + 64 + lane] = fmaxf(fmaf(z1[zb + 64 + lane], sc2, sh2), 0.0f);
    A2[b + 384 + 96 + lane] = fmaxf(fmaf(z1[zb + 96 + lane], sc3, sh3), 0.0f);
}

// ------ head: inline BN preps (mlp2 + bn2) + relu + dot ----------------------
__global__ __launch_bounds__(256)
void k_final(const float* __restrict__ ow, const float* __restrict__ ob,
             const float* __restrict__ sumM, const float* __restrict__ sqM,
             const float* __restrict__ mg, const float* __restrict__ mb,
             const float* __restrict__ sumG, const float* __restrict__ sqG,
             const float* __restrict__ gg, const float* __restrict__ gb,
             float* __restrict__ out) {
    __shared__ float scm[128], shm[128], scg[128], shg[128];
    int tid = threadIdx.x;
    const float invN = 1.0f / (float)NN;
    if (tid < 128) {
        float m = sumM[tid] * invN;
        float var = sqM[tid] * invN - m * m;
        float s = mg[tid] * rsqrtf(var + EPS);
        scm[tid] = s;
        shm[tid] = mb[tid] - m * s;
    } else {
        int c = tid - 128;
        float m = sumG[c] * invN;
        float var = sqG[c] * invN - m * m;
        float s = gg[c] * rsqrtf(var + EPS);
        scg[c] = s;
        shg[c] = gb[c] - m * s;
    }
    __syncthreads();

    int g = blockIdx.x * blockDim.x + tid;
    int node = g >> 5;
    int lane = g & 31;
    if (node >= NN) return;
    float4 a  = *(const float4*)&g_zmlp[(long)node * 128 + lane * 4];
    float4 sm = *(const float4*)&scm[lane * 4];
    float4 hm = *(const float4*)&shm[lane * 4];
    float4 w1 = *(const float4*)&ow[lane * 4];
    float4 b  = *(const float4*)&g_agg2[(long)node * 128 + lane * 4];
    float4 sg = *(const float4*)&scg[lane * 4];
    float4 hg = *(const float4*)&shg[lane * 4];
    float4 w2 = *(const float4*)&ow[128 + lane * 4];
    float sum =
        fmaxf(fmaf(a.x, sm.x, hm.x), 0.f) * w1.x + fmaxf(fmaf(a.y, sm.y, hm.y), 0.f) * w1.y +
        fmaxf(fmaf(a.z, sm.z, hm.z), 0.f) * w1.z + fmaxf(fmaf(a.w, sm.w, hm.w), 0.f) * w1.w +
        fmaxf(fmaf(b.x, sg.x, hg.x), 0.f) * w2.x + fmaxf(fmaf(b.y, sg.y, hg.y), 0.f) * w2.y +
        fmaxf(fmaf(b.z, sg.z, hg.z), 0.f) * w2.z + fmaxf(fmaf(b.w, sg.w, hg.w), 0.f) * w2.w;
#pragma unroll
    for (int off = 16; off > 0; off >>= 1) sum += __shfl_down_sync(0xffffffffu, sum, off);
    if (lane == 0) out[node] = sum + ob[0];
}

// ---------------- host -------------------------------------------------------
extern "C" void kernel_launch(void* const* d_in, const int* in_sizes, int n_in,
                              void* d_out, int out_size) {
    const float* x       = (const float*)d_in[0];
    const float* hsd     = (const float*)d_in[1];
    const int*   ei      = (const int*)d_in[2];
    const int*   et      = (const int*)d_in[3];
    const float* mlp_w1  = (const float*)d_in[4];
    const float* mlp_b1  = (const float*)d_in[5];
    const float* mlp_g1  = (const float*)d_in[6];
    const float* mlp_be1 = (const float*)d_in[7];
    const float* mlp_w2  = (const float*)d_in[8];
    const float* mlp_b2  = (const float*)d_in[9];
    const float* mlp_g2  = (const float*)d_in[10];
    const float* mlp_be2 = (const float*)d_in[11];
    const float* rg1_wrel  = (const float*)d_in[12];
    const float* rg1_wroot = (const float*)d_in[13];
    const float* rg1_b     = (const float*)d_in[14];
    const float* bn1_g     = (const float*)d_in[15];
    const float* bn1_b     = (const float*)d_in[16];
    const float* rg2_wrel  = (const float*)d_in[17];
    const float* rg2_wroot = (const float*)d_in[18];
    const float* rg2_b     = (const float*)d_in[19];
    const float* bn2_g     = (const float*)d_in[20];
    const float* bn2_b     = (const float*)d_in[21];
    const float* out_w     = (const float*)d_in[22];
    const float* out_b     = (const float*)d_in[23];
    const int* src = ei;
    const int* dst = ei + EE;
    float* out = (float*)d_out;

    float *bufA, *A1, *zmlp, *A2, *agg1, *agg2, *wcat, *sum, *sq;
    int *hist;
    cudaGetSymbolAddress((void**)&bufA, g_bufA);
    cudaGetSymbolAddress((void**)&A1, g_A1);
    cudaGetSymbolAddress((void**)&zmlp, g_zmlp);
    cudaGetSymbolAddress((void**)&A2, g_A2);
    cudaGetSymbolAddress((void**)&agg1, g_agg1);
    cudaGetSymbolAddress((void**)&agg2, g_agg2);
    cudaGetSymbolAddress((void**)&wcat, g_wcat);
    cudaGetSymbolAddress((void**)&sum, g_sum);
    cudaGetSymbolAddress((void**)&sq, g_sq);
    cudaGetSymbolAddress((void**)&hist, g_hist);

    const int T = 256;
    float* wcat1 = wcat;
    float* wcat2 = wcat + 256 * 128;
    int nodeGrid = (NN * 32) / T;              // 12500, exact
    int gyAll = (NN + BM - 1) / BM;            // 782

    cudaStream_t s0 = 0, sB;
    cudaStreamCreate(&sB);
    cudaEvent_t evFork, evJoin;
    cudaEventCreateWithFlags(&evFork, cudaEventDisableTiming);
    cudaEventCreateWithFlags(&evJoin, cudaEventDisableTiming);

    // --- prologue on s0 ---
    k_zero_f2<<<4, T, 0, s0>>>(sum, sq, 1024);
    cudaEventRecord(evFork, s0);
    cudaStreamWaitEvent(sB, evFork, 0);

    // --- track B: CSR + weights + GNN chain ---
    k_zero_i<<<(NN + T - 1) / T, T, 0, sB>>>(hist, NN);
    k_prep_w<<<(4 * 128 * 128 + T - 1) / T, T, 0, sB>>>(rg1_wrel, rg1_wroot,
                                                        rg2_wrel, rg2_wroot);
    k_hist<<<(EE + T - 1) / T, T, 0, sB>>>(dst);
    k_scan1<<<NB1, 512, 0, sB>>>();
    k_scan2<<<1, 256, 0, sB>>>();
    k_scan3<<<NB1, 512, 0, sB>>>();
    k_place<<<(EE + T - 1) / T, T, 0, sB>>>(src, dst, et);
    k_asda<<<nodeGrid, T, 0, sB>>>(x, hsd);
    k_agg1<<<nodeGrid, T, 0, sB>>>();
    // rgcn1: z1(raw) = A1 @ wcat1 + b, stats fused
    sgemm_bias<<<dim3(1, gyAll, 1), T, 0, sB>>>(A1, wcat1, rg1_b, agg1, NN, 256, 128, 256,
                                                sum + 512, sq + 512, nullptr, nullptr);
    // build A2 = [aggs of BN1(z1) | BN1(z1)] (BN prep inlined)
    k_agg2<<<nodeGrid, T, 0, sB>>>(agg1, A2, sum + 512, sq + 512, bn1_g, bn1_b);
    // rgcn2: z2(raw) = A2 @ wcat2 + b, stats fused
    sgemm_bias<<<dim3(1, gyAll, 1), T, 0, sB>>>(A2, wcat2, rg2_b, agg2, NN, 512, 128, 512,
                                                sum + 768, sq + 768, nullptr, nullptr);
    cudaEventRecord(evJoin, sB);

    // --- track A: full MLP branch at fork (soaks FMA under B's edge phase) ---
    sgemm_bias<<<dim3(2, gyAll, 1), T, 0, s0>>>(x, mlp_w1, mlp_b1, bufA, NN, 64, 256, 64,
                                                sum + 0, sq + 0, nullptr, nullptr);
    k_bnprep<<<1, 256, 0, s0>>>(sum + 0, sq + 0, mlp_g1, mlp_be1, 256);
    sgemm_bias<<<dim3(1, gyAll, 1), T, 0, s0>>>(bufA, mlp_w2, mlp_b2, zmlp, NN, 256, 128, 256,
                                                sum + 256, sq + 256, sum + 0, sq + 0);

    // join + head (BN preps inlined)
    cudaStreamWaitEvent(s0, evJoin, 0);
    k_final<<<(NN * 32) / T, T, 0, s0>>>(out_w, out_b,
                                         sum + 256, sq + 256, mlp_g2, mlp_be2,
                                         sum + 768, sq + 768, bn2_g, bn2_b, out);
}